// round 11
// baseline (speedup 1.0000x reference)
#include <cuda_runtime.h>
#include <cuda_bf16.h>
#include <math.h>

// ---------------- problem constants ----------------
#define BATCH   32
#define NCLS    60
#define BNC     1920          // BATCH*NCLS
#define DD      256
#define SS      72
#define PM      80            // padded seq for mma tiles
#define NH      8
#define HDIM    32
#define TOPM    20
#define NLAYERS 2
#define MTOT    (BNC*SS)      // 138240 rows
#define LN_EPS  1e-5f

// ---------------- scratch (device globals; no cudaMalloc allowed) ----------------
__device__ float g_x  [(size_t)MTOT*DD];        // activations fp32 (residual/mean)
__device__ float g_qkv[(size_t)MTOT*3*DD];      // qkv projections fp32
__device__ float g_tmp[(size_t)MTOT*DD];        // proj + residual (pre-LN)
__device__ __nv_bfloat16 g_xh[(size_t)MTOT*DD]; // x split hi (A of qkv gemm)
__device__ __nv_bfloat16 g_xl[(size_t)MTOT*DD]; // x split lo
__device__ __nv_bfloat16 g_ah[(size_t)MTOT*DD]; // attn-out split hi (A of proj gemm)
__device__ __nv_bfloat16 g_al[(size_t)MTOT*DD];
// transposed split weights: [N][K] layout, K=256
__device__ __nv_bfloat16 g_wqh[2*768*256], g_wql[2*768*256];
__device__ __nv_bfloat16 g_wph[2*256*256], g_wpl[2*256*256];

// ---------------- helpers ----------------
__device__ __forceinline__ void split_bf16(float v, __nv_bfloat16& h, __nv_bfloat16& l) {
    h = __float2bfloat16(v);
    l = __float2bfloat16(v - __bfloat162float(h));
}
__device__ __forceinline__ unsigned pack2(__nv_bfloat16 a, __nv_bfloat16 b) {
    __nv_bfloat162 p = __halves2bfloat162(a, b);   // .x low 16 bits
    return *(unsigned*)&p;
}

__device__ __forceinline__ void mma_bf16(float* c, const unsigned* a, const unsigned* b) {
    asm volatile(
        "mma.sync.aligned.m16n8k16.row.col.f32.bf16.bf16.f32 "
        "{%0,%1,%2,%3}, {%4,%5,%6,%7}, {%8,%9}, {%0,%1,%2,%3};"
        : "+f"(c[0]), "+f"(c[1]), "+f"(c[2]), "+f"(c[3])
        : "r"(a[0]), "r"(a[1]), "r"(a[2]), "r"(a[3]),
          "r"(b[0]), "r"(b[1]));
}

__device__ __forceinline__ void cp_async16(void* smem, const void* gmem) {
    unsigned s = (unsigned)__cvta_generic_to_shared(smem);
    asm volatile("cp.async.cg.shared.global [%0], [%1], 16;\n" :: "r"(s), "l"(gmem));
}
__device__ __forceinline__ void cp_commit() { asm volatile("cp.async.commit_group;\n"); }
__device__ __forceinline__ void cp_wait1()  { asm volatile("cp.async.wait_group 1;\n"); }
__device__ __forceinline__ void cp_wait0()  { asm volatile("cp.async.wait_group 0;\n"); }

// ---------------- kernel 0: weight split + transpose  out[n][k] = split(w[k][n]) ------
__global__ void k_wsplitT(const float* __restrict__ w, __nv_bfloat16* __restrict__ oh,
                          __nv_bfloat16* __restrict__ ol, int K, int N) {
    int idx = blockIdx.x * 256 + threadIdx.x;
    if (idx >= K * N) return;
    int n = idx / K, k = idx - n * K;
    float v = w[(size_t)k * N + n];
    __nv_bfloat16 h, l;
    split_bf16(v, h, l);
    oh[idx] = h;
    ol[idx] = l;
}

// ---------------- kernel 1: transpose (BNC,D,S)->(BNC,S,D) + pos embed + split -------
__global__ __launch_bounds__(256) void k_transpose(const float* __restrict__ f,
                                                   const float* __restrict__ pos,
                                                   float* __restrict__ x,
                                                   __nv_bfloat16* __restrict__ xh,
                                                   __nv_bfloat16* __restrict__ xl) {
    __shared__ float t[32][33];
    int b  = blockIdx.x;
    int s0 = blockIdx.y * 32;
    int d0 = blockIdx.z * 32;
    int tx = threadIdx.x, ty = threadIdx.y;       // block (32,8)
    const float* fb = f + (size_t)b * DD * SS;
    #pragma unroll
    for (int i = 0; i < 4; i++) {
        int d = d0 + ty + i*8;
        int s = s0 + tx;
        t[ty + i*8][tx] = (s < SS) ? fb[d * SS + s] : 0.f;
    }
    __syncthreads();
    #pragma unroll
    for (int i = 0; i < 4; i++) {
        int s = s0 + ty + i*8;
        int d = d0 + tx;
        if (s < SS) {
            size_t o = (size_t)(b * SS + s) * DD + d;
            float v = t[tx][ty + i*8] + pos[s * DD + d];
            x[o] = v;
            __nv_bfloat16 h, l;
            split_bf16(v, h, l);
            xh[o] = h; xl[o] = l;
        }
    }
}

// ---------------- kernel 2: bf16x3 tensor-core GEMM, 2-stage cp.async pipeline -------
// (validated R10) C = A @ BT^T + bias (+res), operands pre-split bf16 hi/lo.
__global__ __launch_bounds__(256, 2) void k_gemm_bf16x3(
        const __nv_bfloat16* __restrict__ Ah, const __nv_bfloat16* __restrict__ Al,
        const __nv_bfloat16* __restrict__ BTh, const __nv_bfloat16* __restrict__ BTl,
        const float* __restrict__ bias, const float* __restrict__ res,
        float* __restrict__ C, int N) {
    extern __shared__ unsigned su[];
    const int tid  = threadIdx.x;
    const int m0   = blockIdx.y * 128;
    const int n0   = blockIdx.x * 64;
    const int warp = tid >> 5, lane = tid & 31;
    const int wm   = warp & 3;
    const int wn   = warp >> 2;
    const int g    = lane >> 2;
    const int t    = lane & 3;

    float acc[2][4][4];
    #pragma unroll
    for (int i = 0; i < 2; i++)
        #pragma unroll
        for (int j = 0; j < 4; j++)
            #pragma unroll
            for (int r = 0; r < 4; r++) acc[i][j][r] = 0.f;

    auto load_stage = [&](int st, int k0) {
        #pragma unroll
        for (int i = 0; i < 2; i++) {
            int idx = tid + i * 256;
            int m = idx >> 2, c = idx & 3;
            size_t go = (size_t)(m0 + m) * 256 + k0 + c * 8;
            cp_async16(&su[st * 2560 + m * 20 + c * 4],        Ah + go);
            cp_async16(&su[5120 + st * 2560 + m * 20 + c * 4], Al + go);
        }
        {
            int n = tid >> 2, c = tid & 3;
            size_t go = (size_t)(n0 + n) * 256 + k0 + c * 8;
            cp_async16(&su[10240 + st * 1280 + n * 20 + c * 4], BTh + go);
            cp_async16(&su[12800 + st * 1280 + n * 20 + c * 4], BTl + go);
        }
        cp_commit();
    };

    load_stage(0, 0);
    #pragma unroll
    for (int kc = 0; kc < 8; kc++) {
        const int st = kc & 1;
        if (kc < 7) load_stage(st ^ 1, (kc + 1) * 32);
        if (kc < 7) cp_wait1(); else cp_wait0();
        __syncthreads();
        #pragma unroll
        for (int ks = 0; ks < 2; ks++) {
            const int kcol = ks * 8;
            unsigned ah[2][4], al[2][4], bh[4][2], bl[4][2];
            #pragma unroll
            for (int mt = 0; mt < 2; mt++) {
                int base = st * 2560 + (wm * 32 + mt * 16 + g) * 20 + kcol;
                ah[mt][0] = su[base + t];
                ah[mt][1] = su[base + 160 + t];
                ah[mt][2] = su[base + t + 4];
                ah[mt][3] = su[base + 160 + t + 4];
                al[mt][0] = su[5120 + base + t];
                al[mt][1] = su[5120 + base + 160 + t];
                al[mt][2] = su[5120 + base + t + 4];
                al[mt][3] = su[5120 + base + 160 + t + 4];
            }
            #pragma unroll
            for (int nt = 0; nt < 4; nt++) {
                int base = 10240 + st * 1280 + (wn * 32 + nt * 8 + g) * 20 + kcol;
                bh[nt][0] = su[base + t];
                bh[nt][1] = su[base + t + 4];
                bl[nt][0] = su[2560 + base + t];
                bl[nt][1] = su[2560 + base + t + 4];
            }
            #pragma unroll
            for (int mt = 0; mt < 2; mt++)
                #pragma unroll
                for (int nt = 0; nt < 4; nt++) {
                    mma_bf16(acc[mt][nt], ah[mt], bl[nt]);
                    mma_bf16(acc[mt][nt], al[mt], bh[nt]);
                    mma_bf16(acc[mt][nt], ah[mt], bh[nt]);
                }
        }
        __syncthreads();
    }
    #pragma unroll
    for (int mt = 0; mt < 2; mt++) {
        #pragma unroll
        for (int nt = 0; nt < 4; nt++) {
            int m = m0 + wm * 32 + mt * 16 + g;
            int n = n0 + wn * 32 + nt * 8 + 2 * t;
            float bx = bias[n], by = bias[n + 1];
            float2 o0 = make_float2(acc[mt][nt][0] + bx, acc[mt][nt][1] + by);
            float2 o1 = make_float2(acc[mt][nt][2] + bx, acc[mt][nt][3] + by);
            if (res) {
                float2 r0 = *(const float2*)(res + (size_t)m * N + n);
                float2 r1 = *(const float2*)(res + (size_t)(m + 8) * N + n);
                o0.x += r0.x; o0.y += r0.y;
                o1.x += r1.x; o1.y += r1.y;
            }
            *(float2*)(C + (size_t)m * N + n)       = o0;
            *(float2*)(C + (size_t)(m + 8) * N + n) = o1;
        }
    }
}

// ---------------- kernel 3: tensor-core top-M attention per (batch, head) -----------
// smem u32 layout:
//   sc  : float [80][81]              @ 0      (6480 u32)
//   A   = 6480:
//     phase1: qh [80][17] @A+0, ql @A+1360, kh @A+2720, kl @A+4080   (5440)
//     phase2: ph [80][41] @A+0, pl @A+3280, vh [32][41] @A+6560, vl @A+7872 (9184)
// total = 15664 u32 = 62656 B dynamic smem
__global__ __launch_bounds__(256) void k_attn_mma(const float* __restrict__ qkv,
                                                  __nv_bfloat16* __restrict__ oh,
                                                  __nv_bfloat16* __restrict__ ol) {
    extern __shared__ unsigned sm[];
    float* sc    = (float*)sm;
    unsigned* A  = sm + 6480;
    const int b = blockIdx.x, h = blockIdx.y;
    const int tid = threadIdx.x;
    const int warp = tid >> 5, lane = tid & 31;
    const int g = lane >> 2, t = lane & 3;
    const float* base = qkv + (size_t)b * SS * 768 + h * HDIM;

    // ---- phase 0: load q,k -> split bf16 hi/lo smem (zero pad rows 72..79)
    for (int i = tid; i < PM * 16; i += 256) {
        int r = i >> 4, c = i & 15;
        float q0 = 0.f, q1 = 0.f, k0 = 0.f, k1 = 0.f;
        if (r < SS) {
            const float* rp = base + r * 768;
            q0 = rp[2*c];       q1 = rp[2*c + 1];
            k0 = rp[256 + 2*c]; k1 = rp[256 + 2*c + 1];
        }
        __nv_bfloat16 h0, l0, h1, l1;
        split_bf16(q0, h0, l0); split_bf16(q1, h1, l1);
        A[r*17 + c]        = pack2(h0, h1);
        A[1360 + r*17 + c] = pack2(l0, l1);
        split_bf16(k0, h0, l0); split_bf16(k1, h1, l1);
        A[2720 + r*17 + c] = pack2(h0, h1);
        A[4080 + r*17 + c] = pack2(l0, l1);
    }
    __syncthreads();

    // ---- phase 1: scores = Q @ K^T * scale  (45 warp-tiles of 16x8, k=32)
    const float scale = 0.17677669529663687f;   // 32^-0.5
    for (int tile = warp; tile < 45; tile += 8) {
        int mt = tile / 9, nt = tile % 9;
        int mr = mt * 16, nc = nt * 8;
        float acc[4] = {0.f, 0.f, 0.f, 0.f};
        #pragma unroll
        for (int ks = 0; ks < 2; ks++) {
            int co = ks * 8;
            unsigned ah[4], al[4], bh[2], bl[2];
            ah[0] = A[(mr+g)*17 + co + t];       ah[1] = A[(mr+g+8)*17 + co + t];
            ah[2] = A[(mr+g)*17 + co + t + 4];   ah[3] = A[(mr+g+8)*17 + co + t + 4];
            al[0] = A[1360 + (mr+g)*17 + co + t];     al[1] = A[1360 + (mr+g+8)*17 + co + t];
            al[2] = A[1360 + (mr+g)*17 + co + t + 4]; al[3] = A[1360 + (mr+g+8)*17 + co + t + 4];
            bh[0] = A[2720 + (nc+g)*17 + co + t]; bh[1] = A[2720 + (nc+g)*17 + co + t + 4];
            bl[0] = A[4080 + (nc+g)*17 + co + t]; bl[1] = A[4080 + (nc+g)*17 + co + t + 4];
            mma_bf16(acc, ah, bl);
            mma_bf16(acc, al, bh);
            mma_bf16(acc, ah, bh);
        }
        sc[(mr+g)*81   + nc + 2*t]     = acc[0] * scale;
        sc[(mr+g)*81   + nc + 2*t + 1] = acc[1] * scale;
        sc[(mr+g+8)*81 + nc + 2*t]     = acc[2] * scale;
        sc[(mr+g+8)*81 + nc + 2*t + 1] = acc[3] * scale;
    }
    __syncthreads();

    // ---- phase 2a: warps 3-7 load V transposed+split; warps 0-2 softmax rows
    if (tid >= 96) {
        int li = tid - 96;
        for (int i = li; i < 32 * 40; i += 160) {
            int n = i / 40, c = i % 40;
            int s0 = 2*c, s1 = 2*c + 1;
            float v0 = (s0 < SS) ? base[s0 * 768 + 512 + n] : 0.f;
            float v1 = (s1 < SS) ? base[s1 * 768 + 512 + n] : 0.f;
            __nv_bfloat16 h0, l0, h1, l1;
            split_bf16(v0, h0, l0); split_bf16(v1, h1, l1);
            A[6560 + n*41 + c] = pack2(h0, h1);
            A[7872 + n*41 + c] = pack2(l0, l1);
        }
    } else if (tid < SS) {
        float* row = sc + tid * 81;
        float top[TOPM];
        #pragma unroll
        for (int i = 0; i < TOPM; i++) top[i] = -INFINITY;
        for (int c = 0; c < SS; c++) {
            float val = row[c];
            if (val > top[TOPM-1]) {
                #pragma unroll
                for (int i = 0; i < TOPM; i++) {
                    float hi = fmaxf(top[i], val);
                    val      = fminf(top[i], val);
                    top[i]   = hi;
                }
            }
        }
        float thr = top[TOPM-1], mx = top[0];
        float sum = 0.f;
        for (int c = 0; c < SS; c++) {
            float v = row[c];
            float e = (v >= thr) ? __expf(v - mx) : 0.f;
            row[c] = e;
            sum += e;
        }
        float inv = 1.f / sum;
        for (int c = 0; c < SS; c++) row[c] *= inv;
    }
    __syncthreads();

    // ---- phase 2b: split P -> bf16 hi/lo (zero pad rows/cols >= 72)
    for (int i = tid; i < PM * 40; i += 256) {
        int r = i / 40, c = i % 40;
        float p0 = (r < SS && 2*c     < SS) ? sc[r*81 + 2*c]     : 0.f;
        float p1 = (r < SS && 2*c + 1 < SS) ? sc[r*81 + 2*c + 1] : 0.f;
        __nv_bfloat16 h0, l0, h1, l1;
        split_bf16(p0, h0, l0); split_bf16(p1, h1, l1);
        A[r*41 + c]        = pack2(h0, h1);
        A[3280 + r*41 + c] = pack2(l0, l1);
    }
    __syncthreads();

    // ---- phase 3: out = P @ V  (20 warp-tiles of 16x8, k=80), split output
    for (int tile = warp; tile < 20; tile += 8) {
        int mt = tile / 4, nt = tile % 4;
        int mr = mt * 16, nc = nt * 8;
        float acc[4] = {0.f, 0.f, 0.f, 0.f};
        #pragma unroll
        for (int ks = 0; ks < 5; ks++) {
            int co = ks * 8;
            unsigned ah[4], al[4], bh[2], bl[2];
            ah[0] = A[(mr+g)*41 + co + t];       ah[1] = A[(mr+g+8)*41 + co + t];
            ah[2] = A[(mr+g)*41 + co + t + 4];   ah[3] = A[(mr+g+8)*41 + co + t + 4];
            al[0] = A[3280 + (mr+g)*41 + co + t];     al[1] = A[3280 + (mr+g+8)*41 + co + t];
            al[2] = A[3280 + (mr+g)*41 + co + t + 4]; al[3] = A[3280 + (mr+g+8)*41 + co + t + 4];
            bh[0] = A[6560 + (nc+g)*41 + co + t]; bh[1] = A[6560 + (nc+g)*41 + co + t + 4];
            bl[0] = A[7872 + (nc+g)*41 + co + t]; bl[1] = A[7872 + (nc+g)*41 + co + t + 4];
            mma_bf16(acc, ah, bl);
            mma_bf16(acc, al, bh);
            mma_bf16(acc, ah, bh);
        }
        int r0 = mr + g, r1 = mr + g + 8;
        int col = h * HDIM + nc + 2*t;
        if (r0 < SS) {
            size_t o = (size_t)(b * SS + r0) * DD + col;
            __nv_bfloat16 h0, l0, h1, l1;
            split_bf16(acc[0], h0, l0); split_bf16(acc[1], h1, l1);
            *(unsigned*)(oh + o) = pack2(h0, h1);
            *(unsigned*)(ol + o) = pack2(l0, l1);
        }
        if (r1 < SS) {
            size_t o = (size_t)(b * SS + r1) * DD + col;
            __nv_bfloat16 h0, l0, h1, l1;
            split_bf16(acc[2], h0, l0); split_bf16(acc[3], h1, l1);
            *(unsigned*)(oh + o) = pack2(h0, h1);
            *(unsigned*)(ol + o) = pack2(l0, l1);
        }
    }
}

// ---------------- kernel 4: LayerNorm over D=256, warp per row, split outputs --------
__global__ __launch_bounds__(256) void k_ln(const float* __restrict__ y,
                                            const float* __restrict__ g,
                                            const float* __restrict__ bt,
                                            float* __restrict__ x,
                                            __nv_bfloat16* __restrict__ xh,
                                            __nv_bfloat16* __restrict__ xl) {
    const int row  = blockIdx.x * 8 + (threadIdx.x >> 5);
    const int lane = threadIdx.x & 31;
    const float* yr = y + (size_t)row * DD + lane * 8;
    float4 v0 = *(const float4*)(yr);
    float4 v1 = *(const float4*)(yr + 4);
    float s = v0.x + v0.y + v0.z + v0.w + v1.x + v1.y + v1.z + v1.w;
    #pragma unroll
    for (int o = 16; o > 0; o >>= 1) s += __shfl_xor_sync(0xffffffffu, s, o);
    float mu = s * (1.f / DD);
    float d0x = v0.x - mu, d0y = v0.y - mu, d0z = v0.z - mu, d0w = v0.w - mu;
    float d1x = v1.x - mu, d1y = v1.y - mu, d1z = v1.z - mu, d1w = v1.w - mu;
    float s2 = d0x*d0x + d0y*d0y + d0z*d0z + d0w*d0w
             + d1x*d1x + d1y*d1y + d1z*d1z + d1w*d1w;
    #pragma unroll
    for (int o = 16; o > 0; o >>= 1) s2 += __shfl_xor_sync(0xffffffffu, s2, o);
    float rstd = rsqrtf(s2 * (1.f / DD) + LN_EPS);
    float4 g0 = *(const float4*)(g  + lane * 8);
    float4 g1 = *(const float4*)(g  + lane * 8 + 4);
    float4 b0 = *(const float4*)(bt + lane * 8);
    float4 b1 = *(const float4*)(bt + lane * 8 + 4);
    float o0[8];
    o0[0] = d0x * rstd * g0.x + b0.x; o0[1] = d0y * rstd * g0.y + b0.y;
    o0[2] = d0z * rstd * g0.z + b0.z; o0[3] = d0w * rstd * g0.w + b0.w;
    o0[4] = d1x * rstd * g1.x + b1.x; o0[5] = d1y * rstd * g1.y + b1.y;
    o0[6] = d1z * rstd * g1.z + b1.z; o0[7] = d1w * rstd * g1.w + b1.w;
    size_t ro = (size_t)row * DD + lane * 8;
    *(float4*)(x + ro)     = make_float4(o0[0], o0[1], o0[2], o0[3]);
    *(float4*)(x + ro + 4) = make_float4(o0[4], o0[5], o0[6], o0[7]);
    __nv_bfloat16 hh[8], ll[8];
    #pragma unroll
    for (int i = 0; i < 8; i++) split_bf16(o0[i], hh[i], ll[i]);
    *(uint4*)(xh + ro) = *(uint4*)hh;
    *(uint4*)(xl + ro) = *(uint4*)ll;
}

// ---------------- kernel 5: fused seq-mean + classifier MLP ----------------
__global__ __launch_bounds__(128) void k_head(const float* __restrict__ x,
                                              const float* __restrict__ w1,
                                              const float* __restrict__ b1,
                                              const float* __restrict__ w2,
                                              const float* __restrict__ b2,
                                              float* __restrict__ out) {
    __shared__ float xm[DD];
    __shared__ float sh[4];
    const int b = blockIdx.x;
    const int tid = threadIdx.x;          // 128
    float a0 = 0.f, a1 = 0.f;
    const float* xb = x + (size_t)b * SS * DD;
    #pragma unroll 4
    for (int s = 0; s < SS; s++) {
        a0 += xb[s * DD + tid];
        a1 += xb[s * DD + tid + 128];
    }
    xm[tid]       = a0 * (1.f / SS);
    xm[tid + 128] = a1 * (1.f / SS);
    __syncthreads();
    float acc = b1[tid];
    #pragma unroll 8
    for (int k = 0; k < DD; k++)
        acc += xm[k] * w1[k * 128 + tid];
    float contrib = fmaxf(acc, 0.f) * w2[tid];
    const int lane = tid & 31, wid = tid >> 5;
    #pragma unroll
    for (int o = 16; o > 0; o >>= 1) contrib += __shfl_xor_sync(0xffffffffu, contrib, o);
    if (lane == 0) sh[wid] = contrib;
    __syncthreads();
    if (tid == 0)
        out[b] = sh[0] + sh[1] + sh[2] + sh[3] + b2[0];
}

// ---------------- launch ----------------
extern "C" void kernel_launch(void* const* d_in, const int* in_sizes, int n_in,
                              void* d_out, int out_size) {
    const float* feats  = (const float*)d_in[0];   // (1920,256,72)
    const float* pos    = (const float*)d_in[1];   // (1,72,256)
    const float* qkv_w  = (const float*)d_in[2];   // (2,256,768)
    const float* qkv_b  = (const float*)d_in[3];   // (2,768)
    const float* proj_w = (const float*)d_in[4];   // (2,256,256)
    const float* proj_b = (const float*)d_in[5];   // (2,256)
    const float* ln_g   = (const float*)d_in[6];   // (2,256)
    const float* ln_b   = (const float*)d_in[7];   // (2,256)
    const float* cls_w1 = (const float*)d_in[8];   // (256,128)
    const float* cls_b1 = (const float*)d_in[9];   // (128)
    const float* cls_w2 = (const float*)d_in[10];  // (128,1)
    const float* cls_b2 = (const float*)d_in[11];  // (1)
    float* out = (float*)d_out;                    // (32,60) -> 1920

    float *px, *pqkv, *ptmp;
    __nv_bfloat16 *pxh, *pxl, *pah, *pal, *pwqh, *pwql, *pwph, *pwpl;
    cudaGetSymbolAddress((void**)&px,   g_x);
    cudaGetSymbolAddress((void**)&pqkv, g_qkv);
    cudaGetSymbolAddress((void**)&ptmp, g_tmp);
    cudaGetSymbolAddress((void**)&pxh,  g_xh);
    cudaGetSymbolAddress((void**)&pxl,  g_xl);
    cudaGetSymbolAddress((void**)&pah,  g_ah);
    cudaGetSymbolAddress((void**)&pal,  g_al);
    cudaGetSymbolAddress((void**)&pwqh, g_wqh);
    cudaGetSymbolAddress((void**)&pwql, g_wql);
    cudaGetSymbolAddress((void**)&pwph, g_wph);
    cudaGetSymbolAddress((void**)&pwpl, g_wpl);

    // idempotent, graph-capture-safe (not a stream op, not an allocation)
    cudaFuncSetAttribute(k_gemm_bf16x3,
                         cudaFuncAttributeMaxDynamicSharedMemorySize, 61440);
    cudaFuncSetAttribute(k_attn_mma,
                         cudaFuncAttributeMaxDynamicSharedMemorySize, 62656);

    // 0) weight split+transpose (per layer)
    for (int l = 0; l < NLAYERS; l++) {
        k_wsplitT<<<(768*256 + 255)/256, 256>>>(qkv_w + (size_t)l*256*768,
                                                pwqh + (size_t)l*768*256,
                                                pwql + (size_t)l*768*256, 256, 768);
        k_wsplitT<<<(256*256 + 255)/256, 256>>>(proj_w + (size_t)l*256*256,
                                                pwph + (size_t)l*256*256,
                                                pwpl + (size_t)l*256*256, 256, 256);
    }
    // 1) x = transpose(features) + pos (fp32 + split)
    {
        dim3 grid(BNC, 3, 8), blk(32, 8);
        k_transpose<<<grid, blk>>>(feats, pos, px, pxh, pxl);
    }
    // 2) transformer layers
    for (int l = 0; l < NLAYERS; l++) {
        const float* qb = qkv_b  + (size_t)l * 768;
        const float* pb = proj_b + (size_t)l * 256;
        const float* lg = ln_g   + (size_t)l * 256;
        const float* lb = ln_b   + (size_t)l * 256;
        const __nv_bfloat16* wqh = pwqh + (size_t)l * 768 * 256;
        const __nv_bfloat16* wql = pwql + (size_t)l * 768 * 256;
        const __nv_bfloat16* wph = pwph + (size_t)l * 256 * 256;
        const __nv_bfloat16* wpl = pwpl + (size_t)l * 256 * 256;

        {   // qkv = x @ qw + qb
            dim3 grid(768 / 64, MTOT / 128);
            k_gemm_bf16x3<<<grid, 256, 61440>>>(pxh, pxl, wqh, wql, qb, nullptr, pqkv, 768);
        }
        {   // attention (tensor-core) -> split bf16 output
            dim3 grid(BNC, NH);
            k_attn_mma<<<grid, 256, 62656>>>(pqkv, pah, pal);
        }
        {   // tmp = att @ pw + pb + x  (residual)
            dim3 grid(256 / 64, MTOT / 128);
            k_gemm_bf16x3<<<grid, 256, 61440>>>(pah, pal, wph, wpl, pb, px, ptmp, 256);
        }
        // x = LN(tmp) (fp32 + split)
        k_ln<<<MTOT / 8, 256>>>(ptmp, lg, lb, px, pxh, pxl);
    }
    // 3) fused mean + classifier
    k_head<<<BNC, 128>>>(px, cls_w1, cls_b1, cls_w2, cls_b2, out);
}

// round 13
// speedup vs baseline: 1.4547x; 1.4547x over previous
#include <cuda_runtime.h>
#include <cuda_bf16.h>
#include <cuda_fp16.h>
#include <math.h>

// ---------------- problem constants ----------------
#define BATCH   32
#define NCLS    60
#define BNC     1920          // BATCH*NCLS
#define DD      256
#define SS      72
#define NH      8
#define HDIM    32
#define TOPM    20
#define NLAYERS 2
#define MTOT    (BNC*SS)      // 138240 rows
#define LN_EPS  1e-5f

// ---------------- scratch (device globals; no cudaMalloc allowed) ----------------
__device__ float g_x  [(size_t)MTOT*DD];        // activations fp32 (residual/mean)
__device__ float g_qkv[(size_t)MTOT*3*DD];      // qkv projections fp32
__device__ float g_tmp[(size_t)MTOT*DD];        // proj + residual (pre-LN)
__device__ __half          g_xh[(size_t)MTOT*DD]; // x hi (fp16)
__device__ unsigned short  g_x8[(size_t)MTOT*DD]; // x e5m2 pair [f8(h), f8(l)]
__device__ __half          g_ahh[(size_t)MTOT*DD]; // attn-out hi
__device__ unsigned short  g_a8[(size_t)MTOT*DD];  // attn-out e5m2 pair
// transposed weights: [N][K] layout, K=256
__device__ __half         g_wqh[2*768*256];
__device__ unsigned short g_wq8[2*768*256];      // B-side e5m2 pair [f8(l), f8(h)]
__device__ __half         g_wph[2*256*256];
__device__ unsigned short g_wp8[2*256*256];

// ---------------- helpers ----------------
__device__ __forceinline__ void split_f16(float v, __half& h, float& l) {
    h = __float2half_rn(v);
    l = v - __half2float(h);
}
// pack two floats to e5m2 pair: upper byte = up, lower byte = lo
// (e5m2: min normal 2^-14 ~ 6e-5 -> lo residuals (~2e-4) stay representable,
//  unlike e4m3 whose 2^-9 subnormal floor would flush them to zero)
__device__ __forceinline__ unsigned short f8u16(float up, float lo) {
    unsigned short r;
    asm("cvt.rn.satfinite.e5m2x2.f32 %0, %1, %2;" : "=h"(r) : "f"(up), "f"(lo));
    return r;
}
// A-side element (byte0 = f8(h), byte1 = f8(l));  B-side (byte0 = f8(l), byte1 = f8(h))
__device__ __forceinline__ unsigned short f8A(float h, float l) { return f8u16(l, h); }
__device__ __forceinline__ unsigned short f8B(float h, float l) { return f8u16(h, l); }

__device__ __forceinline__ void mma_f16(float* c, const unsigned* a, const unsigned* b) {
    asm volatile(
        "mma.sync.aligned.m16n8k16.row.col.f32.f16.f16.f32 "
        "{%0,%1,%2,%3}, {%4,%5,%6,%7}, {%8,%9}, {%0,%1,%2,%3};"
        : "+f"(c[0]), "+f"(c[1]), "+f"(c[2]), "+f"(c[3])
        : "r"(a[0]), "r"(a[1]), "r"(a[2]), "r"(a[3]),
          "r"(b[0]), "r"(b[1]));
}
__device__ __forceinline__ void mma_fp8(float* c, const unsigned* a, const unsigned* b) {
    asm volatile(
        "mma.sync.aligned.m16n8k32.row.col.f32.e5m2.e5m2.f32 "
        "{%0,%1,%2,%3}, {%4,%5,%6,%7}, {%8,%9}, {%0,%1,%2,%3};"
        : "+f"(c[0]), "+f"(c[1]), "+f"(c[2]), "+f"(c[3])
        : "r"(a[0]), "r"(a[1]), "r"(a[2]), "r"(a[3]),
          "r"(b[0]), "r"(b[1]));
}

__device__ __forceinline__ void cp_async16(void* smem, const void* gmem) {
    unsigned s = (unsigned)__cvta_generic_to_shared(smem);
    asm volatile("cp.async.cg.shared.global [%0], [%1], 16;\n" :: "r"(s), "l"(gmem));
}
__device__ __forceinline__ void cp_commit() { asm volatile("cp.async.commit_group;\n"); }
__device__ __forceinline__ void cp_wait1()  { asm volatile("cp.async.wait_group 1;\n"); }
__device__ __forceinline__ void cp_wait0()  { asm volatile("cp.async.wait_group 0;\n"); }

// ---------------- kernel 0: weight split + transpose  out[n][k] = split(w[k][n]) ------
__global__ void k_wsplitT(const float* __restrict__ w, __half* __restrict__ oh,
                          unsigned short* __restrict__ o8, int K, int N) {
    int idx = blockIdx.x * 256 + threadIdx.x;
    if (idx >= K * N) return;
    int n = idx / K, k = idx - n * K;
    float v = w[(size_t)k * N + n];
    __half h; float l;
    split_f16(v, h, l);
    oh[idx] = h;
    o8[idx] = f8B(__half2float(h), l);
}

// ---------------- kernel 1: transpose (BNC,D,S)->(BNC,S,D) + pos embed + split -------
__global__ __launch_bounds__(256) void k_transpose(const float* __restrict__ f,
                                                   const float* __restrict__ pos,
                                                   float* __restrict__ x,
                                                   __half* __restrict__ xh,
                                                   unsigned short* __restrict__ x8) {
    __shared__ float t[32][33];
    int b  = blockIdx.x;
    int s0 = blockIdx.y * 32;
    int d0 = blockIdx.z * 32;
    int tx = threadIdx.x, ty = threadIdx.y;       // block (32,8)
    const float* fb = f + (size_t)b * DD * SS;
    #pragma unroll
    for (int i = 0; i < 4; i++) {
        int d = d0 + ty + i*8;
        int s = s0 + tx;
        t[ty + i*8][tx] = (s < SS) ? fb[d * SS + s] : 0.f;
    }
    __syncthreads();
    #pragma unroll
    for (int i = 0; i < 4; i++) {
        int s = s0 + ty + i*8;
        int d = d0 + tx;
        if (s < SS) {
            size_t o = (size_t)(b * SS + s) * DD + d;
            float v = t[tx][ty + i*8] + pos[s * DD + d];
            x[o] = v;
            __half h; float l;
            split_f16(v, h, l);
            xh[o] = h;
            x8[o] = f8A(__half2float(h), l);
        }
    }
}

// ---------------- kernel 2: fp16-hi + e5m2-cross tensor-core GEMM -------------------
// C[M,N] = A[M,256] @ BT[N,256]^T + bias (+res).
// Per k16: 1 x m16n8k16.f16 (hi.hi) + 1 x m16n8k32.e5m2 (both cross terms, interleaved:
// per orig-k the A u16 holds [f8(ah),f8(al)], B u16 holds [f8(bl),f8(bh)] so the fp8 mma
// accumulates ah*bl + al*bh). Tile/layout/addressing identical to validated R10 kernel
// (2 bytes per orig-k in all arrays).
__global__ __launch_bounds__(256, 2) void k_gemm_f16f8(
        const __half* __restrict__ Ah, const unsigned short* __restrict__ A8,
        const __half* __restrict__ BTh, const unsigned short* __restrict__ BT8,
        const float* __restrict__ bias, const float* __restrict__ res,
        float* __restrict__ C, int N) {
    extern __shared__ unsigned su[];
    const int tid  = threadIdx.x;
    const int m0   = blockIdx.y * 128;
    const int n0   = blockIdx.x * 64;
    const int warp = tid >> 5, lane = tid & 31;
    const int wm   = warp & 3;
    const int wn   = warp >> 2;
    const int g    = lane >> 2;
    const int t    = lane & 3;

    float acc[2][4][4];
    #pragma unroll
    for (int i = 0; i < 2; i++)
        #pragma unroll
        for (int j = 0; j < 4; j++)
            #pragma unroll
            for (int r = 0; r < 4; r++) acc[i][j][r] = 0.f;

    auto load_stage = [&](int st, int k0) {
        #pragma unroll
        for (int i = 0; i < 2; i++) {
            int idx = tid + i * 256;
            int m = idx >> 2, c = idx & 3;
            size_t go = (size_t)(m0 + m) * 256 + k0 + c * 8;
            cp_async16(&su[st * 2560 + m * 20 + c * 4],        Ah + go);
            cp_async16(&su[5120 + st * 2560 + m * 20 + c * 4], A8 + go);
        }
        {
            int n = tid >> 2, c = tid & 3;
            size_t go = (size_t)(n0 + n) * 256 + k0 + c * 8;
            cp_async16(&su[10240 + st * 1280 + n * 20 + c * 4], BTh + go);
            cp_async16(&su[12800 + st * 1280 + n * 20 + c * 4], BT8 + go);
        }
        cp_commit();
    };

    load_stage(0, 0);
    #pragma unroll
    for (int kc = 0; kc < 8; kc++) {
        const int st = kc & 1;
        if (kc < 7) load_stage(st ^ 1, (kc + 1) * 32);
        if (kc < 7) cp_wait1(); else cp_wait0();
        __syncthreads();
        #pragma unroll
        for (int ks = 0; ks < 2; ks++) {
            const int kcol = ks * 8;
            unsigned ah[2][4], a8[2][4], bh[4][2], b8[4][2];
            #pragma unroll
            for (int mt = 0; mt < 2; mt++) {
                int base = st * 2560 + (wm * 32 + mt * 16 + g) * 20 + kcol;
                ah[mt][0] = su[base + t];
                ah[mt][1] = su[base + 160 + t];
                ah[mt][2] = su[base + t + 4];
                ah[mt][3] = su[base + 160 + t + 4];
                a8[mt][0] = su[5120 + base + t];
                a8[mt][1] = su[5120 + base + 160 + t];
                a8[mt][2] = su[5120 + base + t + 4];
                a8[mt][3] = su[5120 + base + 160 + t + 4];
            }
            #pragma unroll
            for (int nt = 0; nt < 4; nt++) {
                int base = 10240 + st * 1280 + (wn * 32 + nt * 8 + g) * 20 + kcol;
                bh[nt][0] = su[base + t];
                bh[nt][1] = su[base + t + 4];
                b8[nt][0] = su[2560 + base + t];
                b8[nt][1] = su[2560 + base + t + 4];
            }
            #pragma unroll
            for (int mt = 0; mt < 2; mt++)
                #pragma unroll
                for (int nt = 0; nt < 4; nt++) {
                    mma_fp8(acc[mt][nt], a8[mt], b8[nt]);   // cross terms (small) first
                    mma_f16(acc[mt][nt], ah[mt], bh[nt]);   // dominant term
                }
        }
        __syncthreads();
    }
    #pragma unroll
    for (int mt = 0; mt < 2; mt++) {
        #pragma unroll
        for (int nt = 0; nt < 4; nt++) {
            int m = m0 + wm * 32 + mt * 16 + g;
            int n = n0 + wn * 32 + nt * 8 + 2 * t;
            float bx = bias[n], by = bias[n + 1];
            float2 o0 = make_float2(acc[mt][nt][0] + bx, acc[mt][nt][1] + by);
            float2 o1 = make_float2(acc[mt][nt][2] + bx, acc[mt][nt][3] + by);
            if (res) {
                float2 r0 = *(const float2*)(res + (size_t)m * N + n);
                float2 r1 = *(const float2*)(res + (size_t)(m + 8) * N + n);
                o0.x += r0.x; o0.y += r0.y;
                o1.x += r1.x; o1.y += r1.y;
            }
            *(float2*)(C + (size_t)m * N + n)       = o0;
            *(float2*)(C + (size_t)(m + 8) * N + n) = o1;
        }
    }
}

// ---------------- kernel 3: scalar top-M attention per (batch, head) (R10-validated),
//                  output split to fp16-hi + e5m2-pair (A-side of proj GEMM) ---------
__global__ __launch_bounds__(256) void k_attn(const float* __restrict__ qkv,
                                              __half* __restrict__ oh,
                                              unsigned short* __restrict__ o8) {
    __shared__ float sq[80][33];   // q, later reused for v (rows 72..79 stay zero)
    __shared__ float sk[80][33];
    __shared__ float sc[80][81];   // scores -> probs
    const int b = blockIdx.x;
    const int h = blockIdx.y;
    const int tid = threadIdx.x;
    const float* base = qkv + (size_t)b * SS * 768 + h * HDIM;
    for (int idx = tid; idx < 80 * HDIM; idx += 256) {
        int s_ = idx >> 5, d = idx & 31;
        bool ok = s_ < SS;
        sq[s_][d] = ok ? base[s_ * 768 +       d] : 0.f;
        sk[s_][d] = ok ? base[s_ * 768 + 256 + d] : 0.f;
    }
    __syncthreads();
    const int ty = tid >> 4, tx = tid & 15;
    {
        const float scale = 0.17677669529663687f;   // 32^-0.5
        float a[5], bb[5], accs[5][5] = {};
        int r0 = ty * 5, c0 = tx * 5;
        for (int kk = 0; kk < HDIM; kk++) {
            #pragma unroll
            for (int i = 0; i < 5; i++) a[i]  = sq[r0 + i][kk];
            #pragma unroll
            for (int j = 0; j < 5; j++) bb[j] = sk[c0 + j][kk];
            #pragma unroll
            for (int i = 0; i < 5; i++)
                #pragma unroll
                for (int j = 0; j < 5; j++)
                    accs[i][j] += a[i] * bb[j];
        }
        #pragma unroll
        for (int i = 0; i < 5; i++)
            #pragma unroll
            for (int j = 0; j < 5; j++)
                sc[r0 + i][c0 + j] = accs[i][j] * scale;
    }
    __syncthreads();
    for (int idx = tid; idx < SS * HDIM; idx += 256) {
        int s_ = idx >> 5, d = idx & 31;
        sq[s_][d] = base[s_ * 768 + 512 + d];
    }
    if (tid < SS) {
        float top[TOPM];
        #pragma unroll
        for (int i = 0; i < TOPM; i++) top[i] = -INFINITY;
        for (int c = 0; c < SS; c++) {
            float val = sc[tid][c];
            if (val > top[TOPM-1]) {
                #pragma unroll
                for (int i = 0; i < TOPM; i++) {
                    float hi = fmaxf(top[i], val);
                    val      = fminf(top[i], val);
                    top[i]   = hi;
                }
            }
        }
        float thr = top[TOPM-1], mx = top[0];
        float sum = 0.f;
        for (int c = 0; c < SS; c++) {
            float v = sc[tid][c];
            float e = (v >= thr) ? __expf(v - mx) : 0.f;
            sc[tid][c] = e;
            sum += e;
        }
        float inv = 1.f / sum;
        for (int c = 0; c < SS; c++) sc[tid][c] *= inv;
    }
    __syncthreads();
    {
        int r0 = ty * 5, c0 = tx * 2;
        float accs[5][2] = {};
        for (int kk = 0; kk < SS; kk++) {
            float v0 = sq[kk][c0], v1 = sq[kk][c0 + 1];
            #pragma unroll
            for (int i = 0; i < 5; i++) {
                float p = sc[r0 + i][kk];
                accs[i][0] += p * v0;
                accs[i][1] += p * v1;
            }
        }
        #pragma unroll
        for (int i = 0; i < 5; i++) {
            int r = r0 + i;
            if (r < SS) {
                size_t o = (size_t)(b * SS + r) * DD + h * HDIM + c0;
                __half h0, h1; float l0, l1;
                split_f16(accs[i][0], h0, l0);
                split_f16(accs[i][1], h1, l1);
                __half2 hp = __halves2half2(h0, h1);
                *(unsigned*)(oh + o) = *(unsigned*)&hp;
                unsigned short p0 = f8A(__half2float(h0), l0);
                unsigned short p1 = f8A(__half2float(h1), l1);
                *(unsigned*)(o8 + o) = (unsigned)p0 | ((unsigned)p1 << 16);
            }
        }
    }
}

// ---------------- kernel 4: LayerNorm over D=256, warp per row, split outputs --------
__global__ __launch_bounds__(256) void k_ln(const float* __restrict__ y,
                                            const float* __restrict__ g,
                                            const float* __restrict__ bt,
                                            float* __restrict__ x,
                                            __half* __restrict__ xh,
                                            unsigned short* __restrict__ x8) {
    const int row  = blockIdx.x * 8 + (threadIdx.x >> 5);
    const int lane = threadIdx.x & 31;
    const float* yr = y + (size_t)row * DD + lane * 8;
    float4 v0 = *(const float4*)(yr);
    float4 v1 = *(const float4*)(yr + 4);
    float s = v0.x + v0.y + v0.z + v0.w + v1.x + v1.y + v1.z + v1.w;
    #pragma unroll
    for (int o = 16; o > 0; o >>= 1) s += __shfl_xor_sync(0xffffffffu, s, o);
    float mu = s * (1.f / DD);
    float d0x = v0.x - mu, d0y = v0.y - mu, d0z = v0.z - mu, d0w = v0.w - mu;
    float d1x = v1.x - mu, d1y = v1.y - mu, d1z = v1.z - mu, d1w = v1.w - mu;
    float s2 = d0x*d0x + d0y*d0y + d0z*d0z + d0w*d0w
             + d1x*d1x + d1y*d1y + d1z*d1z + d1w*d1w;
    #pragma unroll
    for (int o = 16; o > 0; o >>= 1) s2 += __shfl_xor_sync(0xffffffffu, s2, o);
    float rstd = rsqrtf(s2 * (1.f / DD) + LN_EPS);
    float4 g0 = *(const float4*)(g  + lane * 8);
    float4 g1 = *(const float4*)(g  + lane * 8 + 4);
    float4 b0 = *(const float4*)(bt + lane * 8);
    float4 b1 = *(const float4*)(bt + lane * 8 + 4);
    float o0[8];
    o0[0] = d0x * rstd * g0.x + b0.x; o0[1] = d0y * rstd * g0.y + b0.y;
    o0[2] = d0z * rstd * g0.z + b0.z; o0[3] = d0w * rstd * g0.w + b0.w;
    o0[4] = d1x * rstd * g1.x + b1.x; o0[5] = d1y * rstd * g1.y + b1.y;
    o0[6] = d1z * rstd * g1.z + b1.z; o0[7] = d1w * rstd * g1.w + b1.w;
    size_t ro = (size_t)row * DD + lane * 8;
    *(float4*)(x + ro)     = make_float4(o0[0], o0[1], o0[2], o0[3]);
    *(float4*)(x + ro + 4) = make_float4(o0[4], o0[5], o0[6], o0[7]);
    __half hh[8]; unsigned short pp[8];
    #pragma unroll
    for (int i = 0; i < 8; i++) {
        float l;
        split_f16(o0[i], hh[i], l);
        pp[i] = f8A(__half2float(hh[i]), l);
    }
    *(uint4*)(xh + ro) = *(uint4*)hh;   // 8 half = 16B
    *(uint4*)(x8 + ro) = *(uint4*)pp;   // 8 u16  = 16B
}

// ---------------- kernel 5: fused seq-mean + classifier MLP ----------------
__global__ __launch_bounds__(128) void k_head(const float* __restrict__ x,
                                              const float* __restrict__ w1,
                                              const float* __restrict__ b1,
                                              const float* __restrict__ w2,
                                              const float* __restrict__ b2,
                                              float* __restrict__ out) {
    __shared__ float xm[DD];
    __shared__ float sh[4];
    const int b = blockIdx.x;
    const int tid = threadIdx.x;          // 128
    float a0 = 0.f, a1 = 0.f;
    const float* xb = x + (size_t)b * SS * DD;
    #pragma unroll 4
    for (int s = 0; s < SS; s++) {
        a0 += xb[s * DD + tid];
        a1 += xb[s * DD + tid + 128];
    }
    xm[tid]       = a0 * (1.f / SS);
    xm[tid + 128] = a1 * (1.f / SS);
    __syncthreads();
    float acc = b1[tid];
    #pragma unroll 8
    for (int k = 0; k < DD; k++)
        acc += xm[k] * w1[k * 128 + tid];
    float contrib = fmaxf(acc, 0.f) * w2[tid];
    const int lane = tid & 31, wid = tid >> 5;
    #pragma unroll
    for (int o = 16; o > 0; o >>= 1) contrib += __shfl_xor_sync(0xffffffffu, contrib, o);
    if (lane == 0) sh[wid] = contrib;
    __syncthreads();
    if (tid == 0)
        out[b] = sh[0] + sh[1] + sh[2] + sh[3] + b2[0];
}

// ---------------- launch ----------------
extern "C" void kernel_launch(void* const* d_in, const int* in_sizes, int n_in,
                              void* d_out, int out_size) {
    const float* feats  = (const float*)d_in[0];   // (1920,256,72)
    const float* pos    = (const float*)d_in[1];   // (1,72,256)
    const float* qkv_w  = (const float*)d_in[2];   // (2,256,768)
    const float* qkv_b  = (const float*)d_in[3];   // (2,768)
    const float* proj_w = (const float*)d_in[4];   // (2,256,256)
    const float* proj_b = (const float*)d_in[5];   // (2,256)
    const float* ln_g   = (const float*)d_in[6];   // (2,256)
    const float* ln_b   = (const float*)d_in[7];   // (2,256)
    const float* cls_w1 = (const float*)d_in[8];   // (256,128)
    const float* cls_b1 = (const float*)d_in[9];   // (128)
    const float* cls_w2 = (const float*)d_in[10];  // (128,1)
    const float* cls_b2 = (const float*)d_in[11];  // (1)
    float* out = (float*)d_out;                    // (32,60) -> 1920

    float *px, *pqkv, *ptmp;
    __half *pxh, *pahh, *pwqh, *pwph;
    unsigned short *px8, *pa8, *pwq8, *pwp8;
    cudaGetSymbolAddress((void**)&px,   g_x);
    cudaGetSymbolAddress((void**)&pqkv, g_qkv);
    cudaGetSymbolAddress((void**)&ptmp, g_tmp);
    cudaGetSymbolAddress((void**)&pxh,  g_xh);
    cudaGetSymbolAddress((void**)&px8,  g_x8);
    cudaGetSymbolAddress((void**)&pahh, g_ahh);
    cudaGetSymbolAddress((void**)&pa8,  g_a8);
    cudaGetSymbolAddress((void**)&pwqh, g_wqh);
    cudaGetSymbolAddress((void**)&pwq8, g_wq8);
    cudaGetSymbolAddress((void**)&pwph, g_wph);
    cudaGetSymbolAddress((void**)&pwp8, g_wp8);

    // idempotent, graph-capture-safe (not a stream op, not an allocation)
    cudaFuncSetAttribute(k_gemm_f16f8,
                         cudaFuncAttributeMaxDynamicSharedMemorySize, 61440);

    // 0) weight split+transpose (per layer)
    for (int l = 0; l < NLAYERS; l++) {
        k_wsplitT<<<(768*256 + 255)/256, 256>>>(qkv_w + (size_t)l*256*768,
                                                pwqh + (size_t)l*768*256,
                                                pwq8 + (size_t)l*768*256, 256, 768);
        k_wsplitT<<<(256*256 + 255)/256, 256>>>(proj_w + (size_t)l*256*256,
                                                pwph + (size_t)l*256*256,
                                                pwp8 + (size_t)l*256*256, 256, 256);
    }
    // 1) x = transpose(features) + pos (fp32 + split)
    {
        dim3 grid(BNC, 3, 8), blk(32, 8);
        k_transpose<<<grid, blk>>>(feats, pos, px, pxh, px8);
    }
    // 2) transformer layers
    for (int l = 0; l < NLAYERS; l++) {
        const float* qb = qkv_b  + (size_t)l * 768;
        const float* pb = proj_b + (size_t)l * 256;
        const float* lg = ln_g   + (size_t)l * 256;
        const float* lb = ln_b   + (size_t)l * 256;
        const __half* wqh = pwqh + (size_t)l * 768 * 256;
        const unsigned short* wq8 = pwq8 + (size_t)l * 768 * 256;
        const __half* wph = pwph + (size_t)l * 256 * 256;
        const unsigned short* wp8 = pwp8 + (size_t)l * 256 * 256;

        {   // qkv = x @ qw + qb
            dim3 grid(768 / 64, MTOT / 128);
            k_gemm_f16f8<<<grid, 256, 61440>>>(pxh, px8, wqh, wq8, qb, nullptr, pqkv, 768);
        }
        {   // attention (scalar, validated) -> split output
            dim3 grid(BNC, NH);
            k_attn<<<grid, 256>>>(pqkv, pahh, pa8);
        }
        {   // tmp = att @ pw + pb + x  (residual)
            dim3 grid(256 / 64, MTOT / 128);
            k_gemm_f16f8<<<grid, 256, 61440>>>(pahh, pa8, wph, wp8, pb, px, ptmp, 256);
        }
        // x = LN(tmp) (fp32 + split)
        k_ln<<<MTOT / 8, 256>>>(ptmp, lg, lb, px, pxh, px8);
    }
    // 3) fused mean + classifier
    k_head<<<BNC, 128>>>(px, cls_w1, cls_b1, cls_w2, cls_b2, out);
}

// round 14
// speedup vs baseline: 1.6234x; 1.1159x over previous
#include <cuda_runtime.h>
#include <math.h>

// ---------------- problem constants ----------------
#define BATCH   32
#define NCLS    60
#define BNC     1920          // BATCH*NCLS
#define DD      256
#define SS      72
#define NH      8
#define HDIM    32
#define TOPM    20
#define NLAYERS 2
#define MTOT    (BNC*SS)      // 138240 rows
#define LN_EPS  1e-5f

// ---------------- scratch (device globals; no cudaMalloc allowed) ----------------
__device__ float g_x  [(size_t)MTOT*DD];      // current activations (B,S,D)
__device__ float g_qkv[(size_t)MTOT*3*DD];    // qkv projections
__device__ float g_att[(size_t)MTOT*DD];      // attention output
__device__ float g_tmp[(size_t)MTOT*DD];      // proj + residual (pre-LN)

// ---------------- tf32 helpers ----------------
__device__ __forceinline__ unsigned f2tf32(float f) {
    unsigned r;
    asm("cvt.rna.tf32.f32 %0, %1;" : "=r"(r) : "f"(f));
    return r;
}
__device__ __forceinline__ uint4 cvt4(float4 v) {
    uint4 u;
    u.x = f2tf32(v.x); u.y = f2tf32(v.y);
    u.z = f2tf32(v.z); u.w = f2tf32(v.w);
    return u;
}

__device__ __forceinline__ void mma_tf32(float* c, const unsigned* a, const unsigned* b) {
    asm volatile(
        "mma.sync.aligned.m16n8k8.row.col.f32.tf32.tf32.f32 "
        "{%0,%1,%2,%3}, {%4,%5,%6,%7}, {%8,%9}, {%0,%1,%2,%3};"
        : "+f"(c[0]), "+f"(c[1]), "+f"(c[2]), "+f"(c[3])
        : "r"(a[0]), "r"(a[1]), "r"(a[2]), "r"(a[3]),
          "r"(b[0]), "r"(b[1]));
}

// ---------------- kernel 1: transpose (BNC,D,S)->(BNC,S,D) + pos embed ----------------
__global__ __launch_bounds__(256) void k_transpose(const float* __restrict__ f,
                                                   const float* __restrict__ pos,
                                                   float* __restrict__ x) {
    __shared__ float t[32][33];
    int b  = blockIdx.x;
    int s0 = blockIdx.y * 32;
    int d0 = blockIdx.z * 32;
    int tx = threadIdx.x, ty = threadIdx.y;       // block (32,8)
    const float* fb = f + (size_t)b * DD * SS;
    #pragma unroll
    for (int i = 0; i < 4; i++) {
        int d = d0 + ty + i*8;
        int s = s0 + tx;
        t[ty + i*8][tx] = (s < SS) ? fb[d * SS + s] : 0.f;
    }
    __syncthreads();
    float* xb = x + (size_t)b * SS * DD;
    #pragma unroll
    for (int i = 0; i < 4; i++) {
        int s = s0 + ty + i*8;
        int d = d0 + tx;
        if (s < SS) xb[s * DD + d] = t[tx][ty + i*8] + pos[s * DD + d];
    }
}

// ---------------- kernel 2: tf32 tensor-core GEMM, register-prefetch double buffer ---
// C[M,N] = A[M,256] @ B[256,N] + bias (+res). Numerics identical to R4's kernel
// (same cvt.rna at STS time, same mma order). Only the scheduling changed:
// smem double-buffered, next chunk LDG'd into registers BEFORE the mma section,
// cvt+STS after, one __syncthreads per chunk.
// Dynamic smem (u32): A stage st @ st*4608 ([m][k], row stride 36),
//                     B stage st @ 9216 + st*2304 ([k][n], row stride 72).
__global__ __launch_bounds__(256, 2) void k_gemm_tf32p(const float* __restrict__ A,
                                                       const float* __restrict__ B,
                                                       const float* __restrict__ bias,
                                                       const float* __restrict__ res,
                                                       float* __restrict__ C, int N) {
    extern __shared__ unsigned su[];
    const int tid  = threadIdx.x;
    const int m0   = blockIdx.y * 128;
    const int n0   = blockIdx.x * 64;
    const int warp = tid >> 5, lane = tid & 31;
    const int wm   = warp & 3;    // m offset 32*wm
    const int wn   = warp >> 2;   // n offset 32*wn
    const int g    = lane >> 2;   // 0..7
    const int t    = lane & 3;    // 0..3

    float acc[2][4][4];
    #pragma unroll
    for (int i = 0; i < 2; i++)
        #pragma unroll
        for (int j = 0; j < 4; j++)
            #pragma unroll
            for (int r = 0; r < 4; r++) acc[i][j][r] = 0.f;

    float4 pa[4], pb[2];
    auto ldg_stage = [&](int k0) {
        #pragma unroll
        for (int i = 0; i < 4; i++) {
            int idx = tid + i * 256;
            int m = idx >> 3, kc = idx & 7;
            pa[i] = *(const float4*)(A + (size_t)(m0 + m) * 256 + k0 + kc * 4);
        }
        #pragma unroll
        for (int i = 0; i < 2; i++) {
            int idx = tid + i * 256;
            int k = idx >> 4, nc = idx & 15;
            pb[i] = *(const float4*)(B + (size_t)(k0 + k) * N + n0 + nc * 4);
        }
    };
    auto sts_stage = [&](int st) {
        #pragma unroll
        for (int i = 0; i < 4; i++) {
            int idx = tid + i * 256;
            int m = idx >> 3, kc = idx & 7;
            *(uint4*)&su[st * 4608 + m * 36 + kc * 4] = cvt4(pa[i]);
        }
        #pragma unroll
        for (int i = 0; i < 2; i++) {
            int idx = tid + i * 256;
            int k = idx >> 4, nc = idx & 15;
            *(uint4*)&su[9216 + st * 2304 + k * 72 + nc * 4] = cvt4(pb[i]);
        }
    };

    // prologue: fill stage 0
    ldg_stage(0);
    sts_stage(0);
    __syncthreads();

    #pragma unroll
    for (int kc = 0; kc < 8; kc++) {
        const int st = kc & 1;
        if (kc < 7) ldg_stage((kc + 1) * 32);     // issue global loads early
        // mma over stage st
        #pragma unroll
        for (int ks = 0; ks < 4; ks++) {
            unsigned a[2][4], b[4][2];
            #pragma unroll
            for (int mt = 0; mt < 2; mt++) {
                int mr = wm * 32 + mt * 16;
                int ab = st * 4608 + (mr + g) * 36 + ks * 8;
                a[mt][0] = su[ab + t];
                a[mt][1] = su[ab + 8 * 36 + t];
                a[mt][2] = su[ab + t + 4];
                a[mt][3] = su[ab + 8 * 36 + t + 4];
            }
            #pragma unroll
            for (int nt = 0; nt < 4; nt++) {
                int nc = wn * 32 + nt * 8;
                int bb = 9216 + st * 2304 + (ks * 8 + t) * 72 + nc + g;
                b[nt][0] = su[bb];
                b[nt][1] = su[bb + 4 * 72];
            }
            #pragma unroll
            for (int mt = 0; mt < 2; mt++)
                #pragma unroll
                for (int nt = 0; nt < 4; nt++)
                    mma_tf32(acc[mt][nt], a[mt], b[nt]);
        }
        if (kc < 7) sts_stage(st ^ 1);            // fill the other buffer
        __syncthreads();
    }
    // epilogue: bias (+residual), float2 stores (identical to R4)
    #pragma unroll
    for (int mt = 0; mt < 2; mt++) {
        #pragma unroll
        for (int nt = 0; nt < 4; nt++) {
            int m = m0 + wm * 32 + mt * 16 + g;
            int n = n0 + wn * 32 + nt * 8 + 2 * t;
            float bx = bias[n], by = bias[n + 1];
            float2 o0 = make_float2(acc[mt][nt][0] + bx, acc[mt][nt][1] + by);
            float2 o1 = make_float2(acc[mt][nt][2] + bx, acc[mt][nt][3] + by);
            if (res) {
                float2 r0 = *(const float2*)(res + (size_t)m * N + n);
                float2 r1 = *(const float2*)(res + (size_t)(m + 8) * N + n);
                o0.x += r0.x; o0.y += r0.y;
                o1.x += r1.x; o1.y += r1.y;
            }
            *(float2*)(C + (size_t)m * N + n)       = o0;
            *(float2*)(C + (size_t)(m + 8) * N + n) = o1;
        }
    }
}

// ---------------- kernel 3: scalar top-M attention per (batch, head) ----------------
// (R10-validated scalar path; 80-row zero-padded tiles, no index clamps)
__global__ __launch_bounds__(256) void k_attn(const float* __restrict__ qkv,
                                              float* __restrict__ out) {
    __shared__ float sq[80][33];   // q, later reused for v (rows 72..79 stay zero)
    __shared__ float sk[80][33];
    __shared__ float sc[80][81];   // scores -> probs
    const int b = blockIdx.x;
    const int h = blockIdx.y;
    const int tid = threadIdx.x;
    const float* base = qkv + (size_t)b * SS * 768 + h * HDIM;
    for (int idx = tid; idx < 80 * HDIM; idx += 256) {
        int s_ = idx >> 5, d = idx & 31;
        bool ok = s_ < SS;
        sq[s_][d] = ok ? base[s_ * 768 +       d] : 0.f;
        sk[s_][d] = ok ? base[s_ * 768 + 256 + d] : 0.f;
    }
    __syncthreads();
    const int ty = tid >> 4, tx = tid & 15;
    {
        const float scale = 0.17677669529663687f;   // 32^-0.5
        float a[5], bb[5], accs[5][5] = {};
        int r0 = ty * 5, c0 = tx * 5;
        for (int kk = 0; kk < HDIM; kk++) {
            #pragma unroll
            for (int i = 0; i < 5; i++) a[i]  = sq[r0 + i][kk];
            #pragma unroll
            for (int j = 0; j < 5; j++) bb[j] = sk[c0 + j][kk];
            #pragma unroll
            for (int i = 0; i < 5; i++)
                #pragma unroll
                for (int j = 0; j < 5; j++)
                    accs[i][j] += a[i] * bb[j];
        }
        #pragma unroll
        for (int i = 0; i < 5; i++)
            #pragma unroll
            for (int j = 0; j < 5; j++)
                sc[r0 + i][c0 + j] = accs[i][j] * scale;
    }
    __syncthreads();
    for (int idx = tid; idx < SS * HDIM; idx += 256) {
        int s_ = idx >> 5, d = idx & 31;
        sq[s_][d] = base[s_ * 768 + 512 + d];
    }
    if (tid < SS) {
        float top[TOPM];
        #pragma unroll
        for (int i = 0; i < TOPM; i++) top[i] = -INFINITY;
        for (int c = 0; c < SS; c++) {
            float val = sc[tid][c];
            if (val > top[TOPM-1]) {
                #pragma unroll
                for (int i = 0; i < TOPM; i++) {
                    float hi = fmaxf(top[i], val);
                    val      = fminf(top[i], val);
                    top[i]   = hi;
                }
            }
        }
        float thr = top[TOPM-1], mx = top[0];
        float sum = 0.f;
        for (int c = 0; c < SS; c++) {
            float v = sc[tid][c];
            float e = (v >= thr) ? __expf(v - mx) : 0.f;
            sc[tid][c] = e;
            sum += e;
        }
        float inv = 1.f / sum;
        for (int c = 0; c < SS; c++) sc[tid][c] *= inv;
    }
    __syncthreads();
    {
        int r0 = ty * 5, c0 = tx * 2;
        float accs[5][2] = {};
        for (int kk = 0; kk < SS; kk++) {
            float v0 = sq[kk][c0], v1 = sq[kk][c0 + 1];
            #pragma unroll
            for (int i = 0; i < 5; i++) {
                float p = sc[r0 + i][kk];
                accs[i][0] += p * v0;
                accs[i][1] += p * v1;
            }
        }
        #pragma unroll
        for (int i = 0; i < 5; i++) {
            int r = r0 + i;
            if (r < SS) {
                float* o = out + (size_t)(b * SS + r) * DD + h * HDIM + c0;
                o[0] = accs[i][0];
                o[1] = accs[i][1];
            }
        }
    }
}

// ---------------- kernel 4: LayerNorm over D=256, warp per row ----------------
__global__ __launch_bounds__(256) void k_ln(const float* __restrict__ y,
                                            const float* __restrict__ g,
                                            const float* __restrict__ bt,
                                            float* __restrict__ x) {
    const int row  = blockIdx.x * 8 + (threadIdx.x >> 5);
    const int lane = threadIdx.x & 31;
    const float* yr = y + (size_t)row * DD + lane * 8;
    float4 v0 = *(const float4*)(yr);
    float4 v1 = *(const float4*)(yr + 4);
    float s = v0.x + v0.y + v0.z + v0.w + v1.x + v1.y + v1.z + v1.w;
    #pragma unroll
    for (int o = 16; o > 0; o >>= 1) s += __shfl_xor_sync(0xffffffffu, s, o);
    float mu = s * (1.f / DD);
    float d0x = v0.x - mu, d0y = v0.y - mu, d0z = v0.z - mu, d0w = v0.w - mu;
    float d1x = v1.x - mu, d1y = v1.y - mu, d1z = v1.z - mu, d1w = v1.w - mu;
    float s2 = d0x*d0x + d0y*d0y + d0z*d0z + d0w*d0w
             + d1x*d1x + d1y*d1y + d1z*d1z + d1w*d1w;
    #pragma unroll
    for (int o = 16; o > 0; o >>= 1) s2 += __shfl_xor_sync(0xffffffffu, s2, o);
    float rstd = rsqrtf(s2 * (1.f / DD) + LN_EPS);
    float4 g0 = *(const float4*)(g  + lane * 8);
    float4 g1 = *(const float4*)(g  + lane * 8 + 4);
    float4 b0 = *(const float4*)(bt + lane * 8);
    float4 b1 = *(const float4*)(bt + lane * 8 + 4);
    float4 o0, o1;
    o0.x = d0x * rstd * g0.x + b0.x; o0.y = d0y * rstd * g0.y + b0.y;
    o0.z = d0z * rstd * g0.z + b0.z; o0.w = d0w * rstd * g0.w + b0.w;
    o1.x = d1x * rstd * g1.x + b1.x; o1.y = d1y * rstd * g1.y + b1.y;
    o1.z = d1z * rstd * g1.z + b1.z; o1.w = d1w * rstd * g1.w + b1.w;
    float* xr = x + (size_t)row * DD + lane * 8;
    *(float4*)(xr)     = o0;
    *(float4*)(xr + 4) = o1;
}

// ---------------- kernel 5: fused seq-mean + classifier MLP ----------------
__global__ __launch_bounds__(128) void k_head(const float* __restrict__ x,
                                              const float* __restrict__ w1,
                                              const float* __restrict__ b1,
                                              const float* __restrict__ w2,
                                              const float* __restrict__ b2,
                                              float* __restrict__ out) {
    __shared__ float xm[DD];
    __shared__ float sh[4];
    const int b = blockIdx.x;
    const int tid = threadIdx.x;          // 128
    float a0 = 0.f, a1 = 0.f;
    const float* xb = x + (size_t)b * SS * DD;
    #pragma unroll 4
    for (int s = 0; s < SS; s++) {
        a0 += xb[s * DD + tid];
        a1 += xb[s * DD + tid + 128];
    }
    xm[tid]       = a0 * (1.f / SS);
    xm[tid + 128] = a1 * (1.f / SS);
    __syncthreads();
    float acc = b1[tid];
    #pragma unroll 8
    for (int k = 0; k < DD; k++)
        acc += xm[k] * w1[k * 128 + tid];
    float contrib = fmaxf(acc, 0.f) * w2[tid];
    const int lane = tid & 31, wid = tid >> 5;
    #pragma unroll
    for (int o = 16; o > 0; o >>= 1) contrib += __shfl_xor_sync(0xffffffffu, contrib, o);
    if (lane == 0) sh[wid] = contrib;
    __syncthreads();
    if (tid == 0)
        out[b] = sh[0] + sh[1] + sh[2] + sh[3] + b2[0];
}

// ---------------- launch ----------------
extern "C" void kernel_launch(void* const* d_in, const int* in_sizes, int n_in,
                              void* d_out, int out_size) {
    const float* feats  = (const float*)d_in[0];   // (1920,256,72)
    const float* pos    = (const float*)d_in[1];   // (1,72,256)
    const float* qkv_w  = (const float*)d_in[2];   // (2,256,768)
    const float* qkv_b  = (const float*)d_in[3];   // (2,768)
    const float* proj_w = (const float*)d_in[4];   // (2,256,256)
    const float* proj_b = (const float*)d_in[5];   // (2,256)
    const float* ln_g   = (const float*)d_in[6];   // (2,256)
    const float* ln_b   = (const float*)d_in[7];   // (2,256)
    const float* cls_w1 = (const float*)d_in[8];   // (256,128)
    const float* cls_b1 = (const float*)d_in[9];   // (128)
    const float* cls_w2 = (const float*)d_in[10];  // (128,1)
    const float* cls_b2 = (const float*)d_in[11];  // (1)
    float* out = (float*)d_out;                    // (32,60) -> 1920

    float *px, *pqkv, *patt, *ptmp;
    cudaGetSymbolAddress((void**)&px,   g_x);
    cudaGetSymbolAddress((void**)&pqkv, g_qkv);
    cudaGetSymbolAddress((void**)&patt, g_att);
    cudaGetSymbolAddress((void**)&ptmp, g_tmp);

    // idempotent, graph-capture-safe (not a stream op, not an allocation)
    cudaFuncSetAttribute(k_gemm_tf32p,
                         cudaFuncAttributeMaxDynamicSharedMemorySize, 55296);

    // 1) x = transpose(features) + pos
    {
        dim3 grid(BNC, 3, 8), blk(32, 8);
        k_transpose<<<grid, blk>>>(feats, pos, px);
    }
    // 2) transformer layers
    for (int l = 0; l < NLAYERS; l++) {
        const float* qw = qkv_w  + (size_t)l * 256 * 768;
        const float* qb = qkv_b  + (size_t)l * 768;
        const float* pw = proj_w + (size_t)l * 256 * 256;
        const float* pb = proj_b + (size_t)l * 256;
        const float* lg = ln_g   + (size_t)l * 256;
        const float* lb = ln_b   + (size_t)l * 256;

        {   // qkv = x @ qw + qb
            dim3 grid(768 / 64, MTOT / 128);
            k_gemm_tf32p<<<grid, 256, 55296>>>(px, qw, qb, nullptr, pqkv, 768);
        }
        {   // attention
            dim3 grid(BNC, NH);
            k_attn<<<grid, 256>>>(pqkv, patt);
        }
        {   // tmp = att @ pw + pb + x  (residual)
            dim3 grid(256 / 64, MTOT / 128);
            k_gemm_tf32p<<<grid, 256, 55296>>>(patt, pw, pb, px, ptmp, 256);
        }
        // x = LN(tmp)
        k_ln<<<MTOT / 8, 256>>>(ptmp, lg, lb, px);
    }
    // 3) fused mean + classifier
    k_head<<<BNC, 128>>>(px, cls_w1, cls_b1, cls_w2, cls_b2, out);
}